// round 2
// baseline (speedup 1.0000x reference)
#include <cuda_runtime.h>
#include <math.h>

#define N_ELEMS 16384
#define DELTA_F 0.1f
#define EPS_F 1e-12f

// Scratch (no device allocations allowed in kernel_launch)
__device__ float d_g[N_ELEMS];      // |sigmoid(x) - t|
__device__ float d_loss[N_ELEMS];   // bce-with-logits per element
__device__ int   d_count[N_ELEMS];  // pairwise window counts

// ---------------------------------------------------------------------------
// Kernel 1: per-element prep. g[i], loss[i], and zero the count accumulator
// (must be re-zeroed every launch: graph replays reuse the same buffers).
// ---------------------------------------------------------------------------
__global__ void ghm_prep_kernel(const float* __restrict__ logits,
                                const float* __restrict__ targets) {
    int i = blockIdx.x * blockDim.x + threadIdx.x;
    if (i >= N_ELEMS) return;
    float x = logits[i];
    float t = targets[i];
    float pred = 1.0f / (1.0f + expf(-x));
    d_g[i] = fabsf(pred - t);
    // stable BCE-with-logits: max(x,0) - x*t + log1p(exp(-|x|))
    d_loss[i] = fmaxf(x, 0.0f) - x * t + log1pf(expf(-fabsf(x)));
    d_count[i] = 0;
}

// ---------------------------------------------------------------------------
// Kernel 2: all-pairs window count.
// Grid: (I_TILES, J_CHUNKS). Each block owns 1024 i's (256 threads x R=4)
// and one 1024-wide j-chunk staged in shared memory. Partial counts are
// atomically accumulated into d_count (distinct addresses -> cheap REDG).
// ---------------------------------------------------------------------------
#define CNT_TPB   256
#define CNT_R     4                      // i-values per thread
#define I_TILE    (CNT_TPB * CNT_R)      // 1024
#define J_CHUNK   1024

__global__ __launch_bounds__(CNT_TPB)
void ghm_count_kernel() {
    __shared__ float s_gj[J_CHUNK];

    const int t = threadIdx.x;
    const int ibase = blockIdx.x * I_TILE;
    const int jbase = blockIdx.y * J_CHUNK;

    // Load this thread's R g_i values (coalesced: stride CNT_TPB)
    float gi[CNT_R];
#pragma unroll
    for (int k = 0; k < CNT_R; k++)
        gi[k] = d_g[ibase + k * CNT_TPB + t];

    // Stage the j-chunk into shared memory
#pragma unroll
    for (int m = 0; m < J_CHUNK / CNT_TPB; m++)
        s_gj[m * CNT_TPB + t] = d_g[jbase + m * CNT_TPB + t];
    __syncthreads();

    int c[CNT_R];
#pragma unroll
    for (int k = 0; k < CNT_R; k++) c[k] = 0;

#pragma unroll 8
    for (int j = 0; j < J_CHUNK; j++) {
        float gj = s_gj[j];  // broadcast read, conflict-free
#pragma unroll
        for (int k = 0; k < CNT_R; k++)
            c[k] += (fabsf(gj - gi[k]) <= DELTA_F) ? 1 : 0;
    }

#pragma unroll
    for (int k = 0; k < CNT_R; k++)
        atomicAdd(&d_count[ibase + k * CNT_TPB + t], c[k]);
}

// ---------------------------------------------------------------------------
// Kernel 3: finalize. beta[i] = n / (count[i]/delta + eps); out = mean(beta*loss)
// Single block, 1024 threads, shared-memory tree reduction.
// ---------------------------------------------------------------------------
__global__ __launch_bounds__(1024)
void ghm_finalize_kernel(float* __restrict__ out) {
    __shared__ float s_red[1024];
    const int t = threadIdx.x;

    float acc = 0.0f;
#pragma unroll
    for (int m = 0; m < N_ELEMS / 1024; m++) {
        int i = m * 1024 + t;
        float gd = (float)d_count[i] / DELTA_F;       // count / delta (matches jnp)
        float beta = (float)N_ELEMS / (gd + EPS_F);
        acc += beta * d_loss[i];
    }
    s_red[t] = acc;
    __syncthreads();

    for (int stride = 512; stride >= 32; stride >>= 1) {
        if (t < stride) s_red[t] += s_red[t + stride];
        __syncthreads();
    }
    if (t < 32) {
        float v = s_red[t];
#pragma unroll
        for (int off = 16; off > 0; off >>= 1)
            v += __shfl_down_sync(0xFFFFFFFFu, v, off);
        if (t == 0) out[0] = v / (float)N_ELEMS;
    }
}

// ---------------------------------------------------------------------------
extern "C" void kernel_launch(void* const* d_in, const int* in_sizes, int n_in,
                              void* d_out, int out_size) {
    const float* logits  = (const float*)d_in[0];
    const float* targets = (const float*)d_in[1];
    float* out = (float*)d_out;

    ghm_prep_kernel<<<(N_ELEMS + 255) / 256, 256>>>(logits, targets);

    dim3 grid(N_ELEMS / I_TILE, N_ELEMS / J_CHUNK);  // (16, 16)
    ghm_count_kernel<<<grid, CNT_TPB>>>();

    ghm_finalize_kernel<<<1, 1024>>>(out);
}

// round 3
// speedup vs baseline: 1.6917x; 1.6917x over previous
#include <cuda_runtime.h>
#include <math.h>

#define N_ELEMS 16384
#define NBINS   4096
#define DELTA_F 0.1f
#define EPS_F   1e-12f

// ---- scratch (__device__ globals; no allocations allowed) -------------------
__device__ float d_g[N_ELEMS];
__device__ float d_loss[N_ELEMS];
__device__ int   d_bin[N_ELEMS];
__device__ float d_sorted[N_ELEMS];       // g values grouped by bin
__device__ int   d_histraw[NBINS];
__device__ int   d_binstart[NBINS + 1];   // exclusive prefix
__device__ int   d_cursor[NBINS];         // scatter cursors
__device__ float d_partial[64];

// ---------------------------------------------------------------------------
// K0: zero histogram (graph replays reuse buffers -> must re-zero each launch)
// ---------------------------------------------------------------------------
__global__ void k0_zero_hist() {
    int i = blockIdx.x * blockDim.x + threadIdx.x;
    if (i < NBINS) d_histraw[i] = 0;
}

// ---------------------------------------------------------------------------
// K1: prep. g, loss, bin index, histogram.
// ---------------------------------------------------------------------------
__global__ __launch_bounds__(128)
void k1_prep(const float* __restrict__ logits, const float* __restrict__ targets) {
    int i = blockIdx.x * blockDim.x + threadIdx.x;
    if (i >= N_ELEMS) return;
    float x = logits[i];
    float t = targets[i];
    float pred = 1.0f / (1.0f + expf(-x));
    float g = fabsf(pred - t);
    d_g[i] = g;
    d_loss[i] = fmaxf(x, 0.0f) - x * t + log1pf(expf(-fabsf(x)));
    int b = (int)(g * (float)NBINS);
    b = min(b, NBINS - 1);
    d_bin[i] = b;
    atomicAdd(&d_histraw[b], 1);
}

// ---------------------------------------------------------------------------
// K2: exclusive prefix scan of the 4096-bin histogram (single block, 1024 thr,
// 4 bins/thread). Writes binstart[0..4096] and cursor[].
// ---------------------------------------------------------------------------
__global__ __launch_bounds__(1024)
void k2_scan() {
    __shared__ int s_sum[1024];
    const int t = threadIdx.x;
    const int base = t * 4;
    int c0 = d_histraw[base + 0];
    int c1 = d_histraw[base + 1];
    int c2 = d_histraw[base + 2];
    int c3 = d_histraw[base + 3];
    s_sum[t] = c0 + c1 + c2 + c3;
    __syncthreads();
    // Hillis-Steele inclusive scan over 1024 thread-sums
    for (int off = 1; off < 1024; off <<= 1) {
        int add = (t >= off) ? s_sum[t - off] : 0;
        __syncthreads();
        s_sum[t] += add;
        __syncthreads();
    }
    int run = (t == 0) ? 0 : s_sum[t - 1];  // exclusive
    d_binstart[base + 0] = run; d_cursor[base + 0] = run; run += c0;
    d_binstart[base + 1] = run; d_cursor[base + 1] = run; run += c1;
    d_binstart[base + 2] = run; d_cursor[base + 2] = run; run += c2;
    d_binstart[base + 3] = run; d_cursor[base + 3] = run; run += c3;
    if (t == 1023) d_binstart[NBINS] = run;  // == N_ELEMS
}

// ---------------------------------------------------------------------------
// K3: scatter g into bin-grouped order.
// ---------------------------------------------------------------------------
__global__ __launch_bounds__(256)
void k3_scatter() {
    int i = blockIdx.x * blockDim.x + threadIdx.x;
    if (i >= N_ELEMS) return;
    int b = d_bin[i];
    int pos = atomicAdd(&d_cursor[b], 1);
    d_sorted[pos] = d_g[i];
}

// ---------------------------------------------------------------------------
// K4: range-count query + weighted loss, block partials.
// Interior bins [loBin+3, hiBin-3] are guaranteed all-pass (margin >= 1 bin
// width ~2.4e-4 >> fp32 compare fuzz); bins beyond [loBin-2, hiBin+2] are
// guaranteed all-fail. The +-2 windows absorb bin-index rounding error and are
// checked with the exact fp32 comparison used by the reference.
// ---------------------------------------------------------------------------
__global__ __launch_bounds__(256)
void k4_query() {
    __shared__ float s_red[256];
    const int t = threadIdx.x;
    const int i = blockIdx.x * 256 + t;

    float gi = d_g[i];
    float p = gi * (float)NBINS;
    int loBin = (int)floorf(p - 0.1f * (float)NBINS);
    int hiBin = (int)floorf(p + 0.1f * (float)NBINS);

    // interior: bins [loBin+3, hiBin-3] inclusive
    int iLo = min(max(loBin + 3, 0), NBINS);
    int iHi = min(max(hiBin - 2, 0), NBINS);
    int cnt = (iHi > iLo) ? (d_binstart[iHi] - d_binstart[iLo]) : 0;

    // exact lower window [loBin-2, loBin+2]
    {
        int a = max(loBin - 2, 0), b = min(loBin + 2, NBINS - 1);
        for (int bb = a; bb <= b; bb++) {
            int s = d_binstart[bb], e = d_binstart[bb + 1];
            for (int idx = s; idx < e; idx++)
                cnt += (fabsf(d_sorted[idx] - gi) <= DELTA_F) ? 1 : 0;
        }
    }
    // exact upper window [hiBin-2, hiBin+2]
    {
        int a = max(hiBin - 2, 0), b = min(hiBin + 2, NBINS - 1);
        for (int bb = a; bb <= b; bb++) {
            int s = d_binstart[bb], e = d_binstart[bb + 1];
            for (int idx = s; idx < e; idx++)
                cnt += (fabsf(d_sorted[idx] - gi) <= DELTA_F) ? 1 : 0;
        }
    }

    float GD = (float)cnt / DELTA_F;
    float beta = (float)N_ELEMS / (GD + EPS_F);
    s_red[t] = beta * d_loss[i];
    __syncthreads();

    for (int stride = 128; stride >= 32; stride >>= 1) {
        if (t < stride) s_red[t] += s_red[t + stride];
        __syncthreads();
    }
    if (t < 32) {
        float v = s_red[t];
#pragma unroll
        for (int off = 16; off > 0; off >>= 1)
            v += __shfl_down_sync(0xFFFFFFFFu, v, off);
        if (t == 0) d_partial[blockIdx.x] = v;
    }
}

// ---------------------------------------------------------------------------
// K5: final reduce of 64 partials (fixed order -> deterministic).
// ---------------------------------------------------------------------------
__global__ void k5_final(float* __restrict__ out) {
    if (threadIdx.x == 0) {
        float s = 0.0f;
#pragma unroll
        for (int k = 0; k < 64; k++) s += d_partial[k];
        out[0] = s / (float)N_ELEMS;
    }
}

// ---------------------------------------------------------------------------
extern "C" void kernel_launch(void* const* d_in, const int* in_sizes, int n_in,
                              void* d_out, int out_size) {
    const float* logits  = (const float*)d_in[0];
    const float* targets = (const float*)d_in[1];
    float* out = (float*)d_out;

    k0_zero_hist<<<NBINS / 1024, 1024>>>();
    k1_prep<<<N_ELEMS / 128, 128>>>(logits, targets);
    k2_scan<<<1, 1024>>>();
    k3_scatter<<<N_ELEMS / 256, 256>>>();
    k4_query<<<N_ELEMS / 256, 256>>>();
    k5_final<<<1, 32>>>(out);
}

// round 4
// speedup vs baseline: 1.7029x; 1.0066x over previous
#include <cuda_runtime.h>
#include <math.h>

#define N_ELEMS 16384
#define NBINS   4096
#define NCTA    64
#define TPB     256
#define DELTA_F 0.1f
#define EPS_F   1e-12f

// ---- scratch (__device__ globals; zero-initialized at module load) ----------
__device__ float d_sorted[N_ELEMS];
__device__ int   d_hist[NBINS];        // invariant: zero at launch entry (re-zeroed in P2)
__device__ int   d_binstart[NBINS + 1];
__device__ int   d_cursor[NBINS];
__device__ float d_partial[NCTA];
__device__ volatile int d_sense;       // sense-reversal barrier state (self-resetting)
__device__ int   d_barcnt;

// Grid-wide barrier, CG sync_grids pattern. Called by all threads of all CTAs.
__device__ __forceinline__ void grid_barrier(int* ls) {
    __syncthreads();
    if (threadIdx.x == 0) {
        __threadfence();                      // release CTA's prior global writes
        int s = *ls;
        if (atomicAdd(&d_barcnt, 1) == NCTA - 1) {
            d_barcnt = 0;
            __threadfence();
            d_sense = 1 - s;
        } else {
            while (d_sense == s) { }
            __threadfence();                  // acquire
        }
        *ls = 1 - s;
    }
    __syncthreads();
}

__device__ __forceinline__ int warp_iscan(int v) {
#pragma unroll
    for (int o = 1; o < 32; o <<= 1) {
        int n = __shfl_up_sync(0xffffffffu, v, o);
        if ((threadIdx.x & 31) >= o) v += n;
    }
    return v;
}

__global__ __launch_bounds__(TPB)
void ghm_fused(const float* __restrict__ logits,
               const float* __restrict__ targets,
               float* __restrict__ out) {
    const int t   = threadIdx.x;
    const int bid = blockIdx.x;
    const int i   = bid * TPB + t;      // this thread owns element i throughout

    __shared__ int   s_grp[TPB];
    __shared__ int   s_tmp[2];
    __shared__ int   s_excl[NCTA];
    __shared__ float s_red[TPB];

    int ls = d_sense;  // read current sense before any arrival (all reads precede 1st flip)

    // ---- P0: prep (g, loss in registers) + histogram ----
    float x  = logits[i];
    float tv = targets[i];
    float pred = 1.0f / (1.0f + expf(-x));
    float g    = fabsf(pred - tv);
    float loss = fmaxf(x, 0.0f) - x * tv + log1pf(expf(-fabsf(x)));
    int   myb  = min((int)(g * (float)NBINS), NBINS - 1);
    atomicAdd(&d_hist[myb], 1);

    grid_barrier(&ls);

    // ---- P1: each CTA locally scans the full histogram (no extra barrier) ----
    {
        int gs = 0;
#pragma unroll
        for (int k = 0; k < NBINS / TPB; k++)           // 16 bins per thread
            gs += d_hist[t * (NBINS / TPB) + k];
        s_grp[t] = gs;                                  // 256 group sums (16 bins each)
    }
    __syncthreads();
    int chunkoff;
    {
        // chunk c (64 bins) = groups [4c, 4c+4); exclusive prefix over 64 chunks
        int cs = 0;
        if (t < NCTA)
            cs = s_grp[4 * t] + s_grp[4 * t + 1] + s_grp[4 * t + 2] + s_grp[4 * t + 3];
        int incl = warp_iscan(cs);
        if (t == 31) s_tmp[0] = incl;
        __syncthreads();
        if (t >= 32 && t < 64) incl += s_tmp[0];
        if (t < 64) s_excl[t] = incl - cs;
        __syncthreads();
        chunkoff = s_excl[bid];                         // offset of this CTA's 64-bin chunk
    }
    {
        // exclusive scan within own chunk -> binstart/cursor for bins [bid*64, bid*64+64)
        int h = (t < 64) ? d_hist[bid * 64 + t] : 0;
        int incl = warp_iscan(h);
        if (t == 31) s_tmp[1] = incl;
        __syncthreads();
        if (t >= 32 && t < 64) incl += s_tmp[1];
        if (t < 64) {
            int bs = chunkoff + incl - h;
            d_binstart[bid * 64 + t] = bs;
            d_cursor[bid * 64 + t]   = bs;
        }
        if (i == 0) d_binstart[NBINS] = N_ELEMS;
    }

    grid_barrier(&ls);

    // ---- P2: scatter into bin-grouped order + restore hist=0 invariant ----
    {
        int pos = atomicAdd(&d_cursor[myb], 1);
        d_sorted[pos] = g;
        if (t < 64) d_hist[bid * 64 + t] = 0;           // hist fully consumed above
    }

    grid_barrier(&ls);

    // ---- P3: range-count query (interior via prefix diff, edges exact) ----
    {
        float p = g * (float)NBINS;
        int loBin = (int)floorf(p - 0.1f * (float)NBINS);
        int hiBin = (int)floorf(p + 0.1f * (float)NBINS);
        // bins [loBin+3, hiBin-3] guaranteed all-pass (>=1 bin-width margin);
        // bins outside [loBin-2, hiBin+2] guaranteed all-fail; edges checked
        // with the reference's exact fp32 comparison.
        int iLo = min(max(loBin + 3, 0), NBINS);
        int iHi = min(max(hiBin - 2, 0), NBINS);
        int cnt = (iHi > iLo) ? (d_binstart[iHi] - d_binstart[iLo]) : 0;

        int a0 = max(loBin - 2, 0), b0 = min(loBin + 2, NBINS - 1);
        for (int bb = a0; bb <= b0; bb++) {
            int s = d_binstart[bb], e = d_binstart[bb + 1];
            for (int idx = s; idx < e; idx++)
                cnt += (fabsf(d_sorted[idx] - g) <= DELTA_F) ? 1 : 0;
        }
        int a1 = max(hiBin - 2, 0), b1 = min(hiBin + 2, NBINS - 1);
        for (int bb = a1; bb <= b1; bb++) {
            int s = d_binstart[bb], e = d_binstart[bb + 1];
            for (int idx = s; idx < e; idx++)
                cnt += (fabsf(d_sorted[idx] - g) <= DELTA_F) ? 1 : 0;
        }

        float GD   = (float)cnt / DELTA_F;
        float beta = (float)N_ELEMS / (GD + EPS_F);
        s_red[t] = beta * loss;
    }
    __syncthreads();
    for (int stride = 128; stride >= 32; stride >>= 1) {
        if (t < stride) s_red[t] += s_red[t + stride];
        __syncthreads();
    }
    if (t < 32) {
        float v = s_red[t];
#pragma unroll
        for (int off = 16; off > 0; off >>= 1)
            v += __shfl_down_sync(0xffffffffu, v, off);
        if (t == 0) d_partial[bid] = v;
    }

    grid_barrier(&ls);

    // ---- P4: final fixed-order reduce (deterministic) ----
    if (bid == 0 && t == 0) {
        float s = 0.0f;
#pragma unroll
        for (int k = 0; k < NCTA; k++) s += d_partial[k];
        out[0] = s / (float)N_ELEMS;
    }
}

// ---------------------------------------------------------------------------
extern "C" void kernel_launch(void* const* d_in, const int* in_sizes, int n_in,
                              void* d_out, int out_size) {
    const float* logits  = (const float*)d_in[0];
    const float* targets = (const float*)d_in[1];
    float* out = (float*)d_out;

    ghm_fused<<<NCTA, TPB>>>(logits, targets, out);
}

// round 5
// speedup vs baseline: 2.5927x; 1.5225x over previous
#include <cuda_runtime.h>
#include <math.h>

#define N_ELEMS 16384
#define NBINS   4096
#define NCTA    64
#define TPB     256
#define BPT     (NBINS / TPB)          // 16 bins per thread
#define DELTA_F 0.1f
#define EPS_F   1e-12f
#define FIX_SCALE 4294967296.0         // 2^32

// ---- scratch (__device__ globals; zero-initialized at load) ----------------
__device__ float d_sorted[N_ELEMS];
__device__ int   d_hist[NBINS];               // invariant: zero at launch entry
__device__ int   d_rank[NBINS];               // invariant: zero at launch entry
__device__ unsigned long long d_accum;        // invariant: zero at launch entry
__device__ int   d_done;                      // invariant: zero at launch entry
__device__ volatile int d_sense;
__device__ int   d_barcnt;

// Grid-wide sense-reversal barrier (CG sync_grids pattern).
__device__ __forceinline__ void grid_barrier(int* ls) {
    __syncthreads();
    if (threadIdx.x == 0) {
        __threadfence();
        int s = *ls;
        if (atomicAdd(&d_barcnt, 1) == NCTA - 1) {
            d_barcnt = 0;
            __threadfence();
            d_sense = 1 - s;
        } else {
            while (d_sense == s) { }
            __threadfence();
        }
        *ls = 1 - s;
    }
    __syncthreads();
}

__device__ __forceinline__ int warp_iscan(int v) {
#pragma unroll
    for (int o = 1; o < 32; o <<= 1) {
        int n = __shfl_up_sync(0xffffffffu, v, o);
        if ((threadIdx.x & 31) >= o) v += n;
    }
    return v;
}

__global__ __launch_bounds__(TPB)
void ghm_fused(const float* __restrict__ logits,
               const float* __restrict__ targets,
               float* __restrict__ out) {
    const int t   = threadIdx.x;
    const int bid = blockIdx.x;
    const int i   = bid * TPB + t;     // this thread owns element i throughout

    __shared__ int s_pref[NBINS + 1];  // full exclusive prefix, per-CTA copy
    __shared__ int s_wsum[8];
    __shared__ unsigned long long s_acc[TPB];

    int ls = d_sense;

    // ---- P0: prep + global histogram (REDG, spread addresses) ----
    float x  = logits[i];
    float tv = targets[i];
    float pred = 1.0f / (1.0f + expf(-x));
    float g    = fabsf(pred - tv);
    float loss = fmaxf(x, 0.0f) - x * tv + log1pf(expf(-fabsf(x)));
    int   myb  = min((int)(g * (float)NBINS), NBINS - 1);
    atomicAdd(&d_hist[myb], 1);

    grid_barrier(&ls);                 // B1: histogram complete

    // ---- P1: full exclusive prefix scan into THIS CTA's shared memory ----
    {
        int h[BPT];
        const int4* hv = (const int4*)&d_hist[t * BPT];
        int4 a = hv[0], b = hv[1], c = hv[2], d = hv[3];
        h[0]=a.x; h[1]=a.y; h[2]=a.z; h[3]=a.w;
        h[4]=b.x; h[5]=b.y; h[6]=b.z; h[7]=b.w;
        h[8]=c.x; h[9]=c.y; h[10]=c.z; h[11]=c.w;
        h[12]=d.x; h[13]=d.y; h[14]=d.z; h[15]=d.w;
        int tot = 0;
#pragma unroll
        for (int k = 0; k < BPT; k++) tot += h[k];
        int incl = warp_iscan(tot);
        if ((t & 31) == 31) s_wsum[t >> 5] = incl;
        __syncthreads();
        if (t < 8) {
            int w = s_wsum[t];
#pragma unroll
            for (int o = 1; o < 8; o <<= 1) {
                int n = __shfl_up_sync(0xffu, w, o);
                if (t >= o) w += n;
            }
            s_wsum[t] = w;
        }
        __syncthreads();
        int base = incl - tot + ((t >> 5) ? s_wsum[(t >> 5) - 1] : 0);
#pragma unroll
        for (int k = 0; k < BPT; k++) {
            s_pref[t * BPT + k] = base;
            base += h[k];
        }
        if (t == TPB - 1) s_pref[NBINS] = N_ELEMS;
    }
    __syncthreads();

    // ---- P2: scatter (no barrier needed: d_rank starts at 0, atomics commute)
    {
        int pos = s_pref[myb] + atomicAdd(&d_rank[myb], 1);
        d_sorted[pos] = g;
    }

    grid_barrier(&ls);                 // B2: all scatters complete

    // restore zero-invariants (hist & rank fully consumed by now)
    if (t < NBINS / NCTA) {            // 64 bins per CTA
        d_hist[bid * (NBINS / NCTA) + t] = 0;
        d_rank[bid * (NBINS / NCTA) + t] = 0;
    }

    // ---- P3: range-count query ----
    // Interior bins [loBin+3, hiBin-3] guaranteed all-pass (>=1 bin-width
    // margin vs fp32 compare fuzz); bins outside [loBin-2, hiBin+2] guaranteed
    // all-fail; edge windows checked with the reference's exact fp32 compare.
    unsigned long long fixterm;
    {
        float p = g * (float)NBINS;
        int loBin = (int)floorf(p - 0.1f * (float)NBINS);
        int hiBin = (int)floorf(p + 0.1f * (float)NBINS);

        int iLo = min(max(loBin + 3, 0), NBINS);
        int iHi = min(max(hiBin - 2, 0), NBINS);
        int cnt = (iHi > iLo) ? (s_pref[iHi] - s_pref[iLo]) : 0;

        // lower edge window: bins [loBin-2, loBin+2] -> contiguous element run
        {
            int a0 = max(loBin - 2, 0), b0 = min(loBin + 2, NBINS - 1);
            if (b0 >= a0) {
                int s = s_pref[a0], e = s_pref[b0 + 1];
                for (int idx = s; idx < e; idx++)
                    cnt += (fabsf(d_sorted[idx] - g) <= DELTA_F) ? 1 : 0;
            }
        }
        // upper edge window: bins [hiBin-2, hiBin+2]
        {
            int a1 = max(hiBin - 2, 0), b1 = min(hiBin + 2, NBINS - 1);
            if (b1 >= a1) {
                int s = s_pref[a1], e = s_pref[b1 + 1];
                for (int idx = s; idx < e; idx++)
                    cnt += (fabsf(d_sorted[idx] - g) <= DELTA_F) ? 1 : 0;
            }
        }

        float GD   = (float)cnt / DELTA_F;
        float beta = (float)N_ELEMS / (GD + EPS_F);
        float term = beta * loss;      // >= 0
        fixterm = (unsigned long long)((double)term * FIX_SCALE);
    }

    // ---- P4: deterministic finalize (integer fixed-point, no barrier) ----
    s_acc[t] = fixterm;
    __syncthreads();
    for (int stride = 128; stride >= 1; stride >>= 1) {
        if (t < stride) s_acc[t] += s_acc[t + stride];
        __syncthreads();
    }
    if (t == 0) {
        atomicAdd(&d_accum, s_acc[0]);
        __threadfence();
        if (atomicAdd(&d_done, 1) == NCTA - 1) {
            __threadfence();
            unsigned long long total = atomicAdd(&d_accum, 0ULL);  // coherent read
            out[0] = (float)(((double)total / FIX_SCALE) / (double)N_ELEMS);
            d_accum = 0ULL;            // restore invariants for next replay
            d_done  = 0;
            __threadfence();
        }
    }
}

// ---------------------------------------------------------------------------
extern "C" void kernel_launch(void* const* d_in, const int* in_sizes, int n_in,
                              void* d_out, int out_size) {
    const float* logits  = (const float*)d_in[0];
    const float* targets = (const float*)d_in[1];
    float* out = (float*)d_out;

    ghm_fused<<<NCTA, TPB>>>(logits, targets, out);
}